// round 4
// baseline (speedup 1.0000x reference)
#include <cuda_runtime.h>

#define DIM   4096
#define RANK  32

// ---------------------------------------------------------------------------
// Single fused kernel: one CTA (256 threads) per row of [B*L, D] = 16384 rows.
//   Non-edited rows: float4 copy with EXPLICIT 4-deep load batching (MLP=4).
//   Edited rows (32 CTAs): in-CTA ReFT edit, overlapped with the copy wave.
// ---------------------------------------------------------------------------
__global__ __launch_bounds__(256) void reft_fused_kernel(
    const float* __restrict__ hs,
    const float* __restrict__ Wsrc_p, const float* __restrict__ bsrc_p,
    const float* __restrict__ Wproj_p,
    const float* __restrict__ Wsrc_s, const float* __restrict__ bsrc_s,
    const float* __restrict__ Wproj_s,
    const int* __restrict__ offsets, const int* __restrict__ seqlens,
    float* __restrict__ out)
{
    const int row = blockIdx.x;            // 0..16383
    const int tid = threadIdx.x;
    const long base = (long)row * DIM;
    const float4* x4 = (const float4*)(hs + base);
    float4*       o4 = (float4*)(out + base);

    const int b = row >> 12;
    const int t = row & 4095;
    const int off = offsets[b];
    const int seq = seqlens[b];

    bool edited = false;
    const float *Wsrc = Wsrc_p, *bias = bsrc_p, *Wproj = Wproj_p;
    if ((unsigned)(t - off) < 4u) {
        edited = true;
    } else if ((unsigned)(t - (off + seq - 4)) < 4u) {
        edited = true;
        Wsrc = Wsrc_s; bias = bsrc_s; Wproj = Wproj_s;
    }

    if (!edited) {
        // Explicit 4-deep batched copy: all loads issued before any store.
        float4 v0 = x4[tid];
        float4 v1 = x4[tid + 256];
        float4 v2 = x4[tid + 512];
        float4 v3 = x4[tid + 768];
        o4[tid]       = v0;
        o4[tid + 256] = v1;
        o4[tid + 512] = v2;
        o4[tid + 768] = v3;
        return;
    }

    // ---------------- edited row ----------------
    __shared__ float4 xs4[DIM / 4];        // 16 KB
    __shared__ float  dots[2 * RANK];
    __shared__ float  s[RANK];

    #pragma unroll
    for (int k = 0; k < 4; k++) {
        int i = tid + k * 256;
        xs4[i] = x4[i];
    }
    __syncthreads();

    // 64 dots: 8 warps x 8 dots each, warp-reduced
    const int warp = tid >> 5;
    const int lane = tid & 31;
    #pragma unroll
    for (int k = 0; k < 8; k++) {
        const int di = warp * 8 + k;       // 0..63
        const float4* W4 = (const float4*)((di < RANK)
                               ? (Wsrc  + (long)di * DIM)
                               : (Wproj + (long)(di - RANK) * DIM));
        float acc = 0.f;
        #pragma unroll 8
        for (int i = lane; i < DIM / 4; i += 32) {
            float4 w  = W4[i];
            float4 xv = xs4[i];
            acc += w.x * xv.x + w.y * xv.y + w.z * xv.z + w.w * xv.w;
        }
        #pragma unroll
        for (int o = 16; o > 0; o >>= 1)
            acc += __shfl_xor_sync(0xffffffff, acc, o);
        if (lane == 0) dots[di] = acc;
    }
    __syncthreads();

    if (tid < RANK) {
        float src  = dots[tid] + bias[tid];
        float proj = dots[tid + RANK];
        s[tid] = (src > 0.f ? src : 0.f) - proj;
    }
    __syncthreads();

    // out = x + s . Wproj
    #pragma unroll
    for (int k = 0; k < 4; k++) {
        int i = tid + k * 256;
        float4 acc = xs4[i];
        #pragma unroll
        for (int r = 0; r < RANK; r++) {
            float4 w = ((const float4*)(Wproj + (long)r * DIM))[i];
            float sr = s[r];
            acc.x += sr * w.x;
            acc.y += sr * w.y;
            acc.z += sr * w.z;
            acc.w += sr * w.w;
        }
        o4[i] = acc;
    }
}

extern "C" void kernel_launch(void* const* d_in, const int* in_sizes, int n_in,
                              void* d_out, int out_size) {
    const float* hs      = (const float*)d_in[0];
    const float* Wsrc_p  = (const float*)d_in[1];
    const float* bsrc_p  = (const float*)d_in[2];
    const float* Wproj_p = (const float*)d_in[3];
    const float* Wsrc_s  = (const float*)d_in[4];
    const float* bsrc_s  = (const float*)d_in[5];
    const float* Wproj_s = (const float*)d_in[6];
    const int*   offsets = (const int*)d_in[7];
    const int*   seqlens = (const int*)d_in[8];
    float* out = (float*)d_out;

    const int nrows = out_size / DIM;      // 16384
    reft_fused_kernel<<<nrows, 256>>>(
        hs, Wsrc_p, bsrc_p, Wproj_p, Wsrc_s, bsrc_s, Wproj_s,
        offsets, seqlens, out);
}

// round 5
// speedup vs baseline: 1.3417x; 1.3417x over previous
#include <cuda_runtime.h>

#define DIM    4096
#define RANK   32
#define NROWS  32          // B(4) * 8 edited rows
#define NDOTS  64          // per row: 32 src + 32 proj
#define NSPLIT 4           // K-dim split per dot

// Partial dot products: [row j][dot di][split]
__device__ float g_part[NROWS * NDOTS * NSPLIT];

// ---------------------------------------------------------------------------
// Kernel A: one warp per (edited row j, dot di, K-split).
// 8192 warp-tasks = 1024 CTAs x 8 warps. Each warp: 256 float4 (8 iters,
// fully unrolled -> MLP ~16 across x & W streams), warp-reduce, write partial.
// ---------------------------------------------------------------------------
__global__ __launch_bounds__(256) void dots_kernel(
    const float* __restrict__ hs,
    const float* __restrict__ Wsrc_p, const float* __restrict__ Wproj_p,
    const float* __restrict__ Wsrc_s, const float* __restrict__ Wproj_s,
    const int* __restrict__ offsets, const int* __restrict__ seqlens)
{
    const int warp = threadIdx.x >> 5;
    const int lane = threadIdx.x & 31;
    const int gw = blockIdx.x * 8 + warp;     // 0..8191
    const int j     = gw >> 8;                // 0..31
    const int di    = (gw >> 2) & 63;         // 0..63
    const int split = gw & 3;                 // 0..3

    const int b = j >> 3;
    const int slot = j & 7;
    int pos;
    const float *Wsrc, *Wproj;
    if (slot < 4) {
        pos = offsets[b] + slot;
        Wsrc = Wsrc_p; Wproj = Wproj_p;
    } else {
        pos = offsets[b] + seqlens[b] - 8 + slot;
        Wsrc = Wsrc_s; Wproj = Wproj_s;
    }

    const float4* x4 = (const float4*)(hs + ((long)b * 4096 + pos) * DIM);
    const float4* W4 = (const float4*)((di < RANK)
                           ? (Wsrc  + (long)di * DIM)
                           : (Wproj + (long)(di - RANK) * DIM));

    const int k0 = split * (DIM / 4 / NSPLIT);   // 256 float4 per split
    float acc = 0.f;
    #pragma unroll
    for (int k = 0; k < 8; k++) {
        const int i = k0 + lane + k * 32;
        float4 w  = W4[i];
        float4 xv = x4[i];
        acc += w.x * xv.x + w.y * xv.y + w.z * xv.z + w.w * xv.w;
    }
    #pragma unroll
    for (int o = 16; o > 0; o >>= 1)
        acc += __shfl_xor_sync(0xffffffff, acc, o);
    if (lane == 0) g_part[(j * NDOTS + di) * NSPLIT + split] = acc;
}

// ---------------------------------------------------------------------------
// Kernel B: one CTA (256 threads) per row. Non-edited: batched float4 copy.
// Edited: s = relu(sum(src parts)+bias) - sum(proj parts); out = x + s·Wproj.
// (Identical structure to the R2 kernel that hit 73.7% DRAM.)
// ---------------------------------------------------------------------------
__global__ __launch_bounds__(256) void fused_kernel(
    const float* __restrict__ hs,
    const float* __restrict__ bsrc_p, const float* __restrict__ Wproj_p,
    const float* __restrict__ bsrc_s, const float* __restrict__ Wproj_s,
    const int* __restrict__ offsets, const int* __restrict__ seqlens,
    float* __restrict__ out)
{
    const int row = blockIdx.x;            // 0..16383
    const int tid = threadIdx.x;
    const long base = (long)row * DIM;
    const float4* x4 = (const float4*)(hs + base);
    float4*       o4 = (float4*)(out + base);

    const int b = row >> 12;
    const int t = row & 4095;
    const int off = offsets[b];
    const int seq = seqlens[b];

    int j = -1;
    const float* bias = bsrc_p;
    const float* Wproj = Wproj_p;
    if ((unsigned)(t - off) < 4u) {
        j = b * 8 + (t - off);
    } else if ((unsigned)(t - (off + seq - 4)) < 4u) {
        j = b * 8 + 4 + (t - (off + seq - 4));
        bias = bsrc_s; Wproj = Wproj_s;
    }

    if (j < 0) {
        #pragma unroll
        for (int k = 0; k < 4; k++) {
            int i = tid + k * 256;
            o4[i] = x4[i];
        }
        return;
    }

    // edited row
    __shared__ float s[RANK];
    if (tid < RANK) {
        const float* ps = &g_part[(j * NDOTS + tid) * NSPLIT];
        const float* pp = &g_part[(j * NDOTS + RANK + tid) * NSPLIT];
        float src  = ps[0] + ps[1] + ps[2] + ps[3] + bias[tid];
        float proj = pp[0] + pp[1] + pp[2] + pp[3];
        s[tid] = (src > 0.f ? src : 0.f) - proj;
    }
    __syncthreads();

    #pragma unroll
    for (int k = 0; k < 4; k++) {
        int i = tid + k * 256;
        float4 acc = x4[i];
        #pragma unroll
        for (int r = 0; r < RANK; r++) {
            float4 w = ((const float4*)(Wproj + (long)r * DIM))[i];
            float sr = s[r];
            acc.x += sr * w.x;
            acc.y += sr * w.y;
            acc.z += sr * w.z;
            acc.w += sr * w.w;
        }
        o4[i] = acc;
    }
}

extern "C" void kernel_launch(void* const* d_in, const int* in_sizes, int n_in,
                              void* d_out, int out_size) {
    const float* hs      = (const float*)d_in[0];
    const float* Wsrc_p  = (const float*)d_in[1];
    const float* bsrc_p  = (const float*)d_in[2];
    const float* Wproj_p = (const float*)d_in[3];
    const float* Wsrc_s  = (const float*)d_in[4];
    const float* bsrc_s  = (const float*)d_in[5];
    const float* Wproj_s = (const float*)d_in[6];
    const int*   offsets = (const int*)d_in[7];
    const int*   seqlens = (const int*)d_in[8];
    float* out = (float*)d_out;

    dots_kernel<<<1024, 256>>>(hs, Wsrc_p, Wproj_p, Wsrc_s, Wproj_s,
                               offsets, seqlens);

    const int nrows = out_size / DIM;      // 16384
    fused_kernel<<<nrows, 256>>>(hs, bsrc_p, Wproj_p, bsrc_s, Wproj_s,
                                 offsets, seqlens, out);
}